// round 11
// baseline (speedup 1.0000x reference)
#include <cuda_runtime.h>

// Fixed problem shape
#define BB 4
#define CC 19
#define HH 256
#define WW 256
#define HW (HH * WW)
#define CHW (CC * HW)
#define RAD 10
#define TS 32
#define EW (TS + 2 * RAD)   // 52
#define NPROD 64            // producer blocks per image (4 rows = 1024 px each)
#define NCONS 256           // consumer blocks total (64 tiles x 4 images)

// Scratch (device globals; flags/accumulators reset by the last consumer)
__device__ float g_ent[BB * HW];
__device__ float g_kl[BB * HW];
__device__ unsigned char g_fg[BB * HW];
__device__ int g_entmax[BB];          // entropy > 0 -> int atomicMax is order-preserving
__device__ double g_acc[BB][4];       // per-image: A=Σb·kl, B=Σb·kl·ent, C=Σb, D=Σb·ent
__device__ unsigned int g_flag[BB * NPROD];  // producer-block completion flags (0/1)
__device__ unsigned int g_done;       // consumer completion counter

// ---------------------------------------------------------------------------
// ONE launch, two block roles:
//   blockIdx.x <  64 : producer — channel math for 4 rows (proven K1 body),
//                      then sets its row-group flag.
//   blockIdx.x >= 64 : consumer — waits on <=14 flags covering its 52-row halo,
//                      then bounded EDT + weights (proven K2 body) + finalize.
// Consumers' latency chain overlaps producers' memory phase.
// Deadlock-free: consumers depend only on linearly-earlier blocks, and
// occupancy 2 guarantees producers always have free SM slots.
// ---------------------------------------------------------------------------
__global__ void __launch_bounds__(1024, 2) ofkd_pc(
    const float* __restrict__ student, const float* __restrict__ teacher,
    float* __restrict__ out)
{
    const int b   = blockIdx.y;
    const int tid = threadIdx.x;

    if (blockIdx.x < NPROD) {
        // ===================== PRODUCER: channel math =======================
        // t,s = logit/4. Z=Σe^t, S=Σt e^t, T=Σs e^t, Zs=Σe^s
        // ent = logZ - S/Z ;  kl = (S-T)/Z - logZ + logZs
        const int p = blockIdx.x * 1024 + tid;       // 4 consecutive rows
        const size_t base = (size_t)b * CHW + p;
        const float* tp = teacher + base;
        const float* sp = student + base;

        float Z = 0.f, S = 0.f, Tt = 0.f, Zs = 0.f;
        float t0, mx = -1e30f;
#pragma unroll
        for (int c = 0; c < CC; c++) {
            float tv = __ldg(tp + (size_t)c * HW) * 0.25f;
            float sv = __ldg(sp + (size_t)c * HW) * 0.25f;
            float e = __expf(tv);
            Z += e;
            S = fmaf(e, tv, S);
            Tt = fmaf(e, sv, Tt);
            Zs += __expf(sv);
            if (c == 0) t0 = tv;
            else        mx = fmaxf(mx, tv);
        }
        const float lZ = __logf(Z);
        const float ent = lZ - S / Z;
        const float kl = (S - Tt) / Z - lZ + __logf(Zs);

        const int idx = b * HW + p;
        g_ent[idx] = ent;
        g_kl[idx] = kl;
        g_fg[idx] = (mx > t0) ? 1 : 0;    // argmax != 0 (ties -> class 0)

        // per-image entropy max (consumed only by the final scalar combine)
        float entm = ent;
#pragma unroll
        for (int o = 16; o > 0; o >>= 1)
            entm = fmaxf(entm, __shfl_xor_sync(0xFFFFFFFF, entm, o));
        __shared__ float smax[32];
        if ((tid & 31) == 0) smax[tid >> 5] = entm;
        __syncthreads();
        if (tid < 32) {
            float m = smax[tid];
#pragma unroll
            for (int o = 16; o > 0; o >>= 1)
                m = fmaxf(m, __shfl_xor_sync(0xFFFFFFFF, m, o));
            if (tid == 0) atomicMax(&g_entmax[b], __float_as_int(m));
        }

        // publish: every thread fences its writes, then one thread sets flag
        __threadfence();
        __syncthreads();
        if (tid == 0)
            *(volatile unsigned int*)&g_flag[b * NPROD + blockIdx.x] = 1u;
        return;
    }

    // ======================= CONSUMER: EDT + weights =========================
    const int t  = blockIdx.x - NPROD;    // 0..63
    const int ti = t >> 3, tj = t & 7;
    const int i0 = ti * TS, j0 = tj * TS;
    const int ty = tid >> 5;              // tile row 0..31
    const int tx = tid & 31;              // tile col 0..31

    // wait for the <=14 producer blocks covering rows [i0-10, i0+41]
    {
        const int lo = max(0, 8 * ti - 3);
        const int hi = min(NPROD - 1, 8 * ti + 10);
        const int pb = lo + tid;
        if (pb <= hi) {
            volatile unsigned int* f = &g_flag[b * NPROD + pb];
            while (*f == 0u) __nanosleep(64);
        }
    }
    __syncthreads();
    __threadfence();    // acquire: order flag observation before data reads

    // prefetch ent/kl for own pixel (valid now; L2-resident)
    const int pidx = b * HW + (i0 + ty) * WW + (j0 + tx);
    const float entv = g_ent[pidx];
    const float klv  = g_kl[pidx];

    __shared__ unsigned char sfg[EW][56];  // fg halo: col cc = global j0-12+cc
    __shared__ unsigned char svv[TS][56];  // vertical min-d^2

    // fg halo: 52 rows x 14 aligned u32 words (single step, tid < 728)
    if (tid < EW * 14) {
        int r = tid / 14, k = tid - r * 14;
        int gi = i0 - RAD + r;
        int g0 = j0 - 12 + 4 * k;          // j0 % 32 == 0 -> g0 % 4 == 0
        unsigned int word = 0;
        if (gi >= 0 && gi < HH) {
            const unsigned char* rowp = g_fg + b * HW + gi * WW;
            if (g0 >= 0 && g0 + 3 < WW) {
                word = *(const unsigned int*)(rowp + g0);
            } else {
#pragma unroll
                for (int bb = 0; bb < 4; bb++) {
                    int gj = g0 + bb;
                    if (gj >= 0 && gj < WW)
                        word |= (unsigned int)rowp[gj] << (8 * bb);
                }
            }
        }
        *(unsigned int*)&sfg[r][4 * k] = word;
    }
    __syncthreads();

    // vertical 21-tap min, byte SIMD (term = 200 - fg*(200-d^2)), 2 chains
    if (tid < TS * 14) {
        int r = tid / 14, wc = (tid - r * 14) * 4;
        unsigned int va = 0xC8C8C8C8u, vb = 0xC8C8C8C8u;
#pragma unroll
        for (int dr = 0; dr < 21; dr += 2) {
            unsigned int f4 = *(const unsigned int*)&sfg[r + dr][wc];
            int d = dr - RAD;
            va = __vminu4(va, 0xC8C8C8C8u - f4 * (unsigned int)(200 - d * d));
        }
#pragma unroll
        for (int dr = 1; dr < 21; dr += 2) {
            unsigned int f4 = *(const unsigned int*)&sfg[r + dr][wc];
            int d = dr - RAD;
            vb = __vminu4(vb, 0xC8C8C8C8u - f4 * (unsigned int)(200 - d * d));
        }
        *(unsigned int*)&svv[r][wc] = __vminu4(va, vb);
    }
    __syncthreads();

    // horizontal 21-tap min: independent byte-LDS, 3 split chains
    // pixel col tx -> smem cc = tx+12; taps tx+2 .. tx+22
    int m0 = 300, m1 = 300, m2 = 300;
#pragma unroll
    for (int s = 0; s < 7; s++) {
        int dd = s - RAD;
        m0 = min(m0, dd * dd + (int)svv[ty][tx + 2 + s]);
    }
#pragma unroll
    for (int s = 7; s < 14; s++) {
        int dd = s - RAD;
        m1 = min(m1, dd * dd + (int)svv[ty][tx + 2 + s]);
    }
#pragma unroll
    for (int s = 14; s < 21; s++) {
        int dd = s - RAD;
        m2 = min(m2, dd * dd + (int)svv[ty][tx + 2 + s]);
    }
    const int d2 = min(m0, min(m1, m2));

    // base weight (conf = 1 - 0.9*ent/Em folded in analytically at finalize)
    float a0 = 0.f, a1 = 0.f, a2 = 0.f, a3 = 0.f;
    if (d2 <= RAD * RAD) {
        float wd = __expf((float)d2 * (-1.0f / 50.0f));   // 2*sigma^2 = 50
        float bnd = 0.f;
        if (sfg[ty + RAD][tx + 12]) {
            bool er = sfg[ty + RAD - 1][tx + 12] && sfg[ty + RAD + 1][tx + 12]
                   && sfg[ty + RAD][tx + 11] && sfg[ty + RAD][tx + 13];
            if (!er) bnd = 1.f;
        }
        float bw = wd * (1.f + bnd);
        a0 = bw * klv;
        a1 = bw * klv * entv;
        a2 = bw;
        a3 = bw * entv;
    }

    // block reduce 4 sums
#pragma unroll
    for (int o = 16; o > 0; o >>= 1) {
        a0 += __shfl_xor_sync(0xFFFFFFFF, a0, o);
        a1 += __shfl_xor_sync(0xFFFFFFFF, a1, o);
        a2 += __shfl_xor_sync(0xFFFFFFFF, a2, o);
        a3 += __shfl_xor_sync(0xFFFFFFFF, a3, o);
    }
    __shared__ float red[4][32];
    if ((tid & 31) == 0) {
        red[0][tid >> 5] = a0; red[1][tid >> 5] = a1;
        red[2][tid >> 5] = a2; red[3][tid >> 5] = a3;
    }
    __syncthreads();

    __shared__ int s_last;
    if (tid < 32) {
        float s0 = red[0][tid], s1 = red[1][tid], s2 = red[2][tid], s3 = red[3][tid];
#pragma unroll
        for (int o = 16; o > 0; o >>= 1) {
            s0 += __shfl_xor_sync(0xFFFFFFFF, s0, o);
            s1 += __shfl_xor_sync(0xFFFFFFFF, s1, o);
            s2 += __shfl_xor_sync(0xFFFFFFFF, s2, o);
            s3 += __shfl_xor_sync(0xFFFFFFFF, s3, o);
        }
        if (tid == 0) {
            atomicAdd(&g_acc[b][0], (double)s0);
            atomicAdd(&g_acc[b][1], (double)s1);
            atomicAdd(&g_acc[b][2], (double)s2);
            atomicAdd(&g_acc[b][3], (double)s3);
            __threadfence();
            unsigned int dn = atomicAdd(&g_done, 1u);
            s_last = (dn == NCONS - 1) ? 1 : 0;
        }
    }
    __syncthreads();

    // last consumer: finalize + reset all state for the next graph replay
    if (s_last) {
        if (tid < BB * NPROD) g_flag[tid] = 0u;
        if (tid == 0) {
            double num = 0.0, den = 0.0;
#pragma unroll
            for (int bb = 0; bb < BB; bb++) {
                double Em = (double)__int_as_float(g_entmax[bb]) + 1e-8;
                num += g_acc[bb][0] - 0.9 * g_acc[bb][1] / Em;
                den += g_acc[bb][2] - 0.9 * g_acc[bb][3] / Em;
                g_acc[bb][0] = 0.0; g_acc[bb][1] = 0.0;
                g_acc[bb][2] = 0.0; g_acc[bb][3] = 0.0;
                g_entmax[bb] = 0;
            }
            out[0] = (float)(16.0 * num / (den + 1e-8));
            atomicExch(&g_done, 0u);
        }
    }
}

extern "C" void kernel_launch(void* const* d_in, const int* in_sizes, int n_in,
                              void* d_out, int out_size)
{
    const float* student = (const float*)d_in[0];
    const float* teacher = (const float*)d_in[1];
    float* out = (float*)d_out;

    ofkd_pc<<<dim3(NPROD + 64, BB), 1024>>>(student, teacher, out);
}

// round 12
// speedup vs baseline: 1.0875x; 1.0875x over previous
#include <cuda_runtime.h>

// Fixed problem shape
#define BB 4
#define CC 19
#define HH 256
#define WW 256
#define HW (HH * WW)
#define CHW (CC * HW)
#define RAD 10
#define TW 32               // tile width (cols)
#define TH 8                // tile height (rows)
#define HR (TH + 2 * RAD)   // 28 halo rows
#define NBLK2 (8 * 32 * BB) // 1024 consumer blocks

// Scratch (device globals; self-resetting each replay)
__device__ float g_ent[BB * HW];
__device__ float g_kl[BB * HW];
__device__ unsigned char g_fg[BB * HW];
__device__ int g_entmax[BB];       // entropy > 0 -> int atomicMax is order-preserving
__device__ double g_acc[BB][4];    // per-image: A=Σb·kl, B=Σb·kl·ent, C=Σb, D=Σb·ent
__device__ unsigned int g_done;    // K2 completion counter

// ---------------------------------------------------------------------------
// K1: 1 pixel/thread, max occupancy, perfectly coalesced. (proven; LTS-bound)
// ---------------------------------------------------------------------------
__global__ void __launch_bounds__(256) k1_channelwise(
    const float* __restrict__ student, const float* __restrict__ teacher)
{
    const int b = blockIdx.y;
    const int p = blockIdx.x * 256 + threadIdx.x;
    const size_t base = (size_t)b * CHW + p;

    float Z = 0.f, S = 0.f, Tt = 0.f, Zs = 0.f;
    float t0, mx = -1e30f;
#pragma unroll
    for (int c = 0; c < CC; c++) {
        float tv = __ldg(teacher + base + (size_t)c * HW) * 0.25f;
        float sv = __ldg(student + base + (size_t)c * HW) * 0.25f;
        float e = __expf(tv);
        Z += e;
        S = fmaf(e, tv, S);
        Tt = fmaf(e, sv, Tt);
        Zs += __expf(sv);
        if (c == 0) t0 = tv;
        else        mx = fmaxf(mx, tv);
    }
    const float lZ = __logf(Z);
    const float ent = lZ - S / Z;
    const float kl = (S - Tt) / Z - lZ + __logf(Zs);

    const int idx = b * HW + p;
    g_ent[idx] = ent;
    g_kl[idx] = kl;
    g_fg[idx] = (mx > t0) ? 1 : 0;   // argmax != 0 (ties -> class 0)

    float entm = ent;
#pragma unroll
    for (int o = 16; o > 0; o >>= 1)
        entm = fmaxf(entm, __shfl_xor_sync(0xFFFFFFFF, entm, o));
    __shared__ float smax[8];
    if ((threadIdx.x & 31) == 0) smax[threadIdx.x >> 5] = entm;
    __syncthreads();
    if (threadIdx.x == 0) {
        float m = smax[0];
#pragma unroll
        for (int w = 1; w < 8; w++) m = fmaxf(m, smax[w]);
        atomicMax(&g_entmax[b], __float_as_int(m));
    }
}

// ---------------------------------------------------------------------------
// K2: bounded EDT + weights + finalize. 32x8 tiles, 256 threads, 1024 blocks
// (~7 CTAs/SM): many small independent phase-chains per SM so LDG/LDS latency
// of one block overlaps ALU of others. Shift-only addressing (16-word rows).
// smem col cc = global col j0-16+cc, cc in [0,64); pixel tx -> cc = tx+16.
// ---------------------------------------------------------------------------
__global__ void __launch_bounds__(256) k2_edt_weights(float* __restrict__ out)
{
    const int b  = blockIdx.z;
    const int i0 = blockIdx.y * TH;
    const int j0 = blockIdx.x * TW;
    const int tid = threadIdx.x;
    const int ty = tid >> 5;           // tile row 0..7
    const int tx = tid & 31;           // tile col 0..31

    // prefetch ent/kl (coalesced; L2-resident) — starts latency early
    const int pidx = b * HW + (i0 + ty) * WW + j0 + tx;
    const float entv = __ldg(g_ent + pidx);
    const float klv  = __ldg(g_kl + pidx);

    __shared__ unsigned char sfg[HR][64];   // fg halo, 16 words/row
    __shared__ unsigned char svv[TH][64];   // vertical min-d^2

    // fg halo: 28 rows x 16 words, 2 steps of 224 threads (shift addressing)
#pragma unroll
    for (int st = 0; st < 2; st++) {
        int t = st * 224 + tid;
        if (tid < 224 && t < HR * 16) {
            int r = t >> 4, k = t & 15;
            int gi = i0 - RAD + r;
            int g0 = j0 - 16 + 4 * k;       // j0 % 32 == 0 -> g0 % 4 == 0
            unsigned int word = 0;
            if (gi >= 0 && gi < HH) {
                const unsigned char* rowp = g_fg + b * HW + gi * WW;
                if (g0 >= 0 && g0 + 3 < WW) {
                    word = *(const unsigned int*)(rowp + g0);
                } else {
#pragma unroll
                    for (int bb = 0; bb < 4; bb++) {
                        int gj = g0 + bb;
                        if (gj >= 0 && gj < WW)
                            word |= (unsigned int)rowp[gj] << (8 * bb);
                    }
                }
            }
            *(unsigned int*)&sfg[r][4 * k] = word;
        }
    }
    __syncthreads();

    // vertical 21-tap min, byte SIMD (term = 200 - fg*(200-d^2)), 2 chains
    if (tid < TH * 16) {
        int r = tid >> 4, wc = (tid & 15) * 4;
        unsigned int va = 0xC8C8C8C8u, vb = 0xC8C8C8C8u;
#pragma unroll
        for (int dr = 0; dr < 21; dr += 2) {
            unsigned int f4 = *(const unsigned int*)&sfg[r + dr][wc];
            int d = dr - RAD;
            va = __vminu4(va, 0xC8C8C8C8u - f4 * (unsigned int)(200 - d * d));
        }
#pragma unroll
        for (int dr = 1; dr < 21; dr += 2) {
            unsigned int f4 = *(const unsigned int*)&sfg[r + dr][wc];
            int d = dr - RAD;
            vb = __vminu4(vb, 0xC8C8C8C8u - f4 * (unsigned int)(200 - d * d));
        }
        *(unsigned int*)&svv[r][wc] = __vminu4(va, vb);
    }
    __syncthreads();

    // horizontal 21-tap min: independent byte-LDS, 3 split chains
    // taps: svv[ty][tx+6 .. tx+26]
    int m0 = 300, m1 = 300, m2 = 300;
#pragma unroll
    for (int s = 0; s < 7; s++) {
        int dd = s - RAD;
        m0 = min(m0, dd * dd + (int)svv[ty][tx + 6 + s]);
    }
#pragma unroll
    for (int s = 7; s < 14; s++) {
        int dd = s - RAD;
        m1 = min(m1, dd * dd + (int)svv[ty][tx + 6 + s]);
    }
#pragma unroll
    for (int s = 14; s < 21; s++) {
        int dd = s - RAD;
        m2 = min(m2, dd * dd + (int)svv[ty][tx + 6 + s]);
    }
    const int d2 = min(m0, min(m1, m2));

    // base weight (conf = 1 - 0.9*ent/Em folded in analytically at finalize)
    float a0 = 0.f, a1 = 0.f, a2 = 0.f, a3 = 0.f;
    if (d2 <= RAD * RAD) {
        float wd = __expf((float)d2 * (-1.0f / 50.0f));   // 2*sigma^2 = 50
        float bnd = 0.f;
        if (sfg[ty + RAD][tx + 16]) {
            bool er = sfg[ty + RAD - 1][tx + 16] && sfg[ty + RAD + 1][tx + 16]
                   && sfg[ty + RAD][tx + 15] && sfg[ty + RAD][tx + 17];
            if (!er) bnd = 1.f;
        }
        float bw = wd * (1.f + bnd);
        a0 = bw * klv;
        a1 = bw * klv * entv;
        a2 = bw;
        a3 = bw * entv;
    }

    // block reduce 4 sums (8 warps)
#pragma unroll
    for (int o = 16; o > 0; o >>= 1) {
        a0 += __shfl_xor_sync(0xFFFFFFFF, a0, o);
        a1 += __shfl_xor_sync(0xFFFFFFFF, a1, o);
        a2 += __shfl_xor_sync(0xFFFFFFFF, a2, o);
        a3 += __shfl_xor_sync(0xFFFFFFFF, a3, o);
    }
    __shared__ float red[4][8];
    if ((tid & 31) == 0) {
        red[0][ty] = a0; red[1][ty] = a1; red[2][ty] = a2; red[3][ty] = a3;
    }
    __syncthreads();

    if (tid == 0) {
        float s0 = 0.f, s1 = 0.f, s2 = 0.f, s3 = 0.f;
#pragma unroll
        for (int w = 0; w < 8; w++) {
            s0 += red[0][w]; s1 += red[1][w]; s2 += red[2][w]; s3 += red[3][w];
        }
        atomicAdd(&g_acc[b][0], (double)s0);
        atomicAdd(&g_acc[b][1], (double)s1);
        atomicAdd(&g_acc[b][2], (double)s2);
        atomicAdd(&g_acc[b][3], (double)s3);
        __threadfence();
        unsigned int t = atomicAdd(&g_done, 1u);
        if (t == NBLK2 - 1) {   // last block: finalize + reset for next replay
            double num = 0.0, den = 0.0;
#pragma unroll
            for (int bb = 0; bb < BB; bb++) {
                double Em = (double)__int_as_float(g_entmax[bb]) + 1e-8;
                num += g_acc[bb][0] - 0.9 * g_acc[bb][1] / Em;
                den += g_acc[bb][2] - 0.9 * g_acc[bb][3] / Em;
                g_acc[bb][0] = 0.0; g_acc[bb][1] = 0.0;
                g_acc[bb][2] = 0.0; g_acc[bb][3] = 0.0;
                g_entmax[bb] = 0;
            }
            out[0] = (float)(16.0 * num / (den + 1e-8));
            atomicExch(&g_done, 0u);
        }
    }
}

extern "C" void kernel_launch(void* const* d_in, const int* in_sizes, int n_in,
                              void* d_out, int out_size)
{
    const float* student = (const float*)d_in[0];
    const float* teacher = (const float*)d_in[1];
    float* out = (float*)d_out;

    k1_channelwise<<<dim3(HW / 256, BB), 256>>>(student, teacher);
    k2_edt_weights<<<dim3(8, 32, BB), 256>>>(out);
}

// round 13
// speedup vs baseline: 1.1954x; 1.0992x over previous
#include <cuda_runtime.h>

// Fixed problem shape
#define BB 4
#define CC 19
#define HH 256
#define WW 256
#define HW (HH * WW)
#define CHW (CC * HW)
#define RAD 10
#define TS 32
#define EW (TS + 2 * RAD)   // 52
#define NBLK 256            // 64 tiles x 4 images; co-resident at occupancy 2

// Device state (monotonic / self-resetting across graph replays)
__device__ unsigned char g_fg[BB * HW];
__device__ int g_entmax[BB];      // entropy > 0 -> int atomicMax is order-preserving
__device__ double g_acc[BB][4];   // per-image: A=Σb·kl, B=Σb·kl·ent, C=Σb, D=Σb·ent
__device__ unsigned int g_arr;        // barrier arrivals (reset by last arriver)
__device__ unsigned int g_release;    // MONOTONIC release epoch (never reset)
__device__ unsigned int g_done;       // finalize election

// ---------------------------------------------------------------------------
// One fused kernel, tile-aligned phases (ent/kl stay in registers; only fg
// crosses the sync). Grid barrier: atomic arrivals + monotonic-epoch release
// polled with VOLATILE LOADS (no atomic-RMW poll storm — the R8 suspect).
// conf is linear in ent, so per-image entropy max enters only the final
// scalar combine by the last-finishing block.
// ---------------------------------------------------------------------------
__global__ void __launch_bounds__(1024, 2) ofkd_fused(
    const float* __restrict__ student, const float* __restrict__ teacher,
    float* __restrict__ out)
{
    const int b   = blockIdx.y;
    const int i0  = (blockIdx.x >> 3) * TS;
    const int j0  = (blockIdx.x & 7) * TS;
    const int tid = threadIdx.x;
    const int ty  = tid >> 5;          // tile row 0..31
    const int tx  = tid & 31;          // tile col 0..31

    // ================= Phase A: channel math, 1 pixel/thread =================
    // t,s = logit/4.  Z=Σe^t, S=Σt e^t, T=Σs e^t, Zs=Σe^s
    // ent = logZ - S/Z ;  kl = (S-T)/Z - logZ + logZs
    float ent, kl;
    {
        const size_t base = (size_t)b * CHW + (size_t)(i0 + ty) * WW + (j0 + tx);
        const float* tp = teacher + base;
        const float* sp = student + base;

        float Z = 0.f, S = 0.f, Tt = 0.f, Zs = 0.f;
        float t0, mx = -1e30f;
#pragma unroll
        for (int c = 0; c < CC; c++) {
            float tv = __ldg(tp + (size_t)c * HW) * 0.25f;
            float sv = __ldg(sp + (size_t)c * HW) * 0.25f;
            float e = __expf(tv);
            Z += e;
            S = fmaf(e, tv, S);
            Tt = fmaf(e, sv, Tt);
            Zs += __expf(sv);
            if (c == 0) t0 = tv;
            else        mx = fmaxf(mx, tv);
        }
        const float lZ = __logf(Z);
        ent = lZ - S / Z;
        kl = (S - Tt) / Z - lZ + __logf(Zs);

        g_fg[b * HW + (i0 + ty) * WW + (j0 + tx)] = (mx > t0) ? 1 : 0;

        // per-image entropy max (consumed only by the final scalar combine)
        float entm = ent;
#pragma unroll
        for (int o = 16; o > 0; o >>= 1)
            entm = fmaxf(entm, __shfl_xor_sync(0xFFFFFFFF, entm, o));
        __shared__ float smax[32];
        if ((tid & 31) == 0) smax[tid >> 5] = entm;
        __syncthreads();
        if (tid < 32) {
            float m = smax[tid];
#pragma unroll
            for (int o = 16; o > 0; o >>= 1)
                m = fmaxf(m, __shfl_xor_sync(0xFFFFFFFF, m, o));
            if (tid == 0) atomicMax(&g_entmax[b], __float_as_int(m));
        }
    }

    // ========== Grid barrier: atomic arrive, volatile-load release ==========
    __threadfence();                    // publish this block's fg writes
    __syncthreads();
    if (tid == 0) {
        // read current epoch BEFORE arriving (monotonic -> replay-safe)
        unsigned int ep = *(volatile unsigned int*)&g_release;
        unsigned int a = atomicAdd(&g_arr, 1u);
        if (a == NBLK - 1) {
            atomicExch(&g_arr, 0u);     // reset for next replay
            __threadfence();
            atomicAdd(&g_release, 1u);  // release everyone
        } else {
            while (*(volatile unsigned int*)&g_release == ep)
                __nanosleep(32);
        }
    }
    __syncthreads();
    __threadfence();                    // acquire before reading peers' fg

    // ================= Phase B: bounded EDT + weights ========================
    __shared__ unsigned char sfg[EW][56];  // fg halo: col cc = global j0-12+cc
    __shared__ unsigned char svv[TS][56];  // vertical min-d^2

    // fg halo: 52 rows x 14 aligned u32 words (single step, tid < 728)
    if (tid < EW * 14) {
        int r = tid / 14, k = tid - r * 14;
        int gi = i0 - RAD + r;
        int g0 = j0 - 12 + 4 * k;          // j0 % 32 == 0 -> g0 % 4 == 0
        unsigned int word = 0;
        if (gi >= 0 && gi < HH) {
            const unsigned char* rowp = g_fg + b * HW + gi * WW;
            if (g0 >= 0 && g0 + 3 < WW) {
                word = *(const unsigned int*)(rowp + g0);
            } else {
#pragma unroll
                for (int bb = 0; bb < 4; bb++) {
                    int gj = g0 + bb;
                    if (gj >= 0 && gj < WW)
                        word |= (unsigned int)rowp[gj] << (8 * bb);
                }
            }
        }
        *(unsigned int*)&sfg[r][4 * k] = word;
    }
    __syncthreads();

    // vertical 21-tap min, byte SIMD (term = 200 - fg*(200-d^2)), 2 chains
    if (tid < TS * 14) {
        int r = tid / 14, wc = (tid - r * 14) * 4;
        unsigned int va = 0xC8C8C8C8u, vb = 0xC8C8C8C8u;
#pragma unroll
        for (int dr = 0; dr < 21; dr += 2) {
            unsigned int f4 = *(const unsigned int*)&sfg[r + dr][wc];
            int d = dr - RAD;
            va = __vminu4(va, 0xC8C8C8C8u - f4 * (unsigned int)(200 - d * d));
        }
#pragma unroll
        for (int dr = 1; dr < 21; dr += 2) {
            unsigned int f4 = *(const unsigned int*)&sfg[r + dr][wc];
            int d = dr - RAD;
            vb = __vminu4(vb, 0xC8C8C8C8u - f4 * (unsigned int)(200 - d * d));
        }
        *(unsigned int*)&svv[r][wc] = __vminu4(va, vb);
    }
    __syncthreads();

    // horizontal 21-tap min: independent byte-LDS, 3 split chains
    // pixel col tx -> smem cc = tx+12; taps tx+2 .. tx+22
    int m0 = 300, m1 = 300, m2 = 300;
#pragma unroll
    for (int s = 0; s < 7; s++) {
        int dd = s - RAD;
        m0 = min(m0, dd * dd + (int)svv[ty][tx + 2 + s]);
    }
#pragma unroll
    for (int s = 7; s < 14; s++) {
        int dd = s - RAD;
        m1 = min(m1, dd * dd + (int)svv[ty][tx + 2 + s]);
    }
#pragma unroll
    for (int s = 14; s < 21; s++) {
        int dd = s - RAD;
        m2 = min(m2, dd * dd + (int)svv[ty][tx + 2 + s]);
    }
    const int d2 = min(m0, min(m1, m2));

    // base weight (conf = 1 - 0.9*ent/Em folded in analytically at finalize)
    float a0 = 0.f, a1 = 0.f, a2 = 0.f, a3 = 0.f;
    if (d2 <= RAD * RAD) {
        float wd = __expf((float)d2 * (-1.0f / 50.0f));   // 2*sigma^2 = 50
        float bnd = 0.f;
        if (sfg[ty + RAD][tx + 12]) {
            bool er = sfg[ty + RAD - 1][tx + 12] && sfg[ty + RAD + 1][tx + 12]
                   && sfg[ty + RAD][tx + 11] && sfg[ty + RAD][tx + 13];
            if (!er) bnd = 1.f;
        }
        float bw = wd * (1.f + bnd);
        a0 = bw * kl;
        a1 = bw * kl * ent;
        a2 = bw;
        a3 = bw * ent;
    }

    // block reduce 4 sums + fused finalize
#pragma unroll
    for (int o = 16; o > 0; o >>= 1) {
        a0 += __shfl_xor_sync(0xFFFFFFFF, a0, o);
        a1 += __shfl_xor_sync(0xFFFFFFFF, a1, o);
        a2 += __shfl_xor_sync(0xFFFFFFFF, a2, o);
        a3 += __shfl_xor_sync(0xFFFFFFFF, a3, o);
    }
    __shared__ float red[4][32];
    if ((tid & 31) == 0) {
        red[0][tid >> 5] = a0; red[1][tid >> 5] = a1;
        red[2][tid >> 5] = a2; red[3][tid >> 5] = a3;
    }
    __syncthreads();

    if (tid < 32) {
        float s0 = red[0][tid], s1 = red[1][tid], s2 = red[2][tid], s3 = red[3][tid];
#pragma unroll
        for (int o = 16; o > 0; o >>= 1) {
            s0 += __shfl_xor_sync(0xFFFFFFFF, s0, o);
            s1 += __shfl_xor_sync(0xFFFFFFFF, s1, o);
            s2 += __shfl_xor_sync(0xFFFFFFFF, s2, o);
            s3 += __shfl_xor_sync(0xFFFFFFFF, s3, o);
        }
        if (tid == 0) {
            atomicAdd(&g_acc[b][0], (double)s0);
            atomicAdd(&g_acc[b][1], (double)s1);
            atomicAdd(&g_acc[b][2], (double)s2);
            atomicAdd(&g_acc[b][3], (double)s3);
            __threadfence();
            unsigned int t = atomicAdd(&g_done, 1u);
            if (t == NBLK - 1) {   // last block: finalize + reset for next replay
                double num = 0.0, den = 0.0;
#pragma unroll
                for (int bb = 0; bb < BB; bb++) {
                    double Em = (double)__int_as_float(g_entmax[bb]) + 1e-8;
                    num += g_acc[bb][0] - 0.9 * g_acc[bb][1] / Em;
                    den += g_acc[bb][2] - 0.9 * g_acc[bb][3] / Em;
                    g_acc[bb][0] = 0.0; g_acc[bb][1] = 0.0;
                    g_acc[bb][2] = 0.0; g_acc[bb][3] = 0.0;
                    g_entmax[bb] = 0;
                }
                out[0] = (float)(16.0 * num / (den + 1e-8));
                atomicExch(&g_done, 0u);
            }
        }
    }
}

extern "C" void kernel_launch(void* const* d_in, const int* in_sizes, int n_in,
                              void* d_out, int out_size)
{
    const float* student = (const float*)d_in[0];
    const float* teacher = (const float*)d_in[1];
    float* out = (float*)d_out;

    ofkd_fused<<<dim3(64, BB), 1024>>>(student, teacher, out);
}